// round 4
// baseline (speedup 1.0000x reference)
#include <cuda_runtime.h>
#include <cuda_bf16.h>
#include <cstdint>

// MatrixExpander: out(16,16,512,512) = kron(A(16,16,64,64), ones(8,8)), fp32.
//
// R4: dual-engine hybrid. R2/R3 both plateaued at ~6.2 TB/s effective write
// via the smem->TMA path with DRAM only ~61% busy -> path-local ceiling
// suspected. Drive BOTH store pipes concurrently:
//   - warps 0-3: warp-per-tile TMA bulk stores (R3 design), tiles [0, 9216)
//   - warps 4-7: coalesced float4 STG.cs grid-stride       , tiles [9216, 16384)
// Split 56/44 per measured solo rates (43.5us vs ~54us for the full job).

__device__ __forceinline__ uint32_t smem_u32(const void* p) {
    uint32_t a;
    asm("{ .reg .u64 t; cvta.to.shared.u64 t, %1; cvt.u32.u64 %0, t; }"
        : "=r"(a) : "l"(p));
    return a;
}

static constexpr uint32_t NTILES    = 16384;          // 16*16*64 (4096 floats each)
static constexpr uint32_t TMA_TILES = 9216;           // handled by TMA warps
static constexpr uint32_t TOTAL_F4  = NTILES * 1024u; // 16,777,216 float4
static constexpr uint32_t STG_BASE  = TMA_TILES * 1024u;

__global__ __launch_bounds__(256)
void expander_hybrid_kernel(const float* __restrict__ A, float* __restrict__ out)
{
    // 4 TMA warps x 2 buffers x 128 float4 (2 KB) = 16 KB
    __shared__ __align__(128) float4 buf[4][2][128];

    const uint32_t wid  = threadIdx.x >> 5;
    const uint32_t lane = threadIdx.x & 31u;

    if (wid < 4) {
        // ---------------- TMA path: warp-per-tile ----------------
        const uint32_t gwarp  = (blockIdx.x << 2) | wid;
        const uint32_t nwarps = gridDim.x << 2;

        uint32_t it = 0;
        for (uint32_t c = gwarp; c < TMA_TILES; c += nwarps, ++it) {
            // Lane l -> float4 slots 4l..4l+3 of the 2 KB expanded row;
            // needs A cols 2l, 2l+1 of row c.
            const float2 av = *reinterpret_cast<const float2*>(
                A + (c << 6) + (lane << 1));

            if (it >= 2) {
                if (lane == 0)
                    asm volatile("cp.async.bulk.wait_group.read 1;" ::: "memory");
                __syncwarp();
            }

            float4* b = buf[wid][it & 1u];
            const float4 v0 = make_float4(av.x, av.x, av.x, av.x);
            const float4 v1 = make_float4(av.y, av.y, av.y, av.y);
            b[(lane << 2) + 0] = v0;
            b[(lane << 2) + 1] = v0;
            b[(lane << 2) + 2] = v1;
            b[(lane << 2) + 3] = v1;
            __syncwarp();

            if (lane == 0) {
                asm volatile("fence.proxy.async.shared::cta;" ::: "memory");
                const uint32_t s = smem_u32(b);
                float* dst = out + ((size_t)c << 12);
                #pragma unroll
                for (int r = 0; r < 8; ++r) {
                    asm volatile(
                        "cp.async.bulk.global.shared::cta.bulk_group [%0], [%1], %2;"
                        :: "l"(dst + (r << 9)), "r"(s), "n"(2048) : "memory");
                }
                asm volatile("cp.async.bulk.commit_group;" ::: "memory");
            }
            __syncwarp();
        }
        if (lane == 0)
            asm volatile("cp.async.bulk.wait_group 0;" ::: "memory");
    } else {
        // ---------------- STG path: coalesced float4 streaming stores ----------------
        float4* out4 = reinterpret_cast<float4*>(out);
        const uint32_t tloc   = (blockIdx.x << 7) + (threadIdx.x - 128u); // 128 STG threads/CTA
        const uint32_t stride = gridDim.x << 7;

        for (uint32_t i = STG_BASE + tloc; i < TOTAL_F4; i += stride) {
            const uint32_t c4  = i & 127u;          // float4 col in row
            const uint32_t row = (i >> 7) & 511u;   // output row
            const uint32_t bc  = i >> 16;           // fused (b,c)
            const float v = __ldg(A + ((bc << 12) | ((row >> 3) << 6) | (c4 >> 1)));
            __stcs(out4 + i, make_float4(v, v, v, v));
        }
    }
}

extern "C" void kernel_launch(void* const* d_in, const int* in_sizes, int n_in,
                              void* d_out, int out_size)
{
    const float* A = (const float*)d_in[0];   // (16,16,64,64) fp32
    float* out = (float*)d_out;               // (16,16,512,512) fp32

    expander_hybrid_kernel<<<1024, 256>>>(A, out);
}

// round 5
// speedup vs baseline: 1.1484x; 1.1484x over previous
#include <cuda_runtime.h>
#include <cuda_bf16.h>
#include <cstdint>

// MatrixExpander: out(16,16,512,512) = kron(A(16,16,64,64), ones(8,8)), fp32.
//
// R5: separate-CTA dual-engine hybrid (fix R4's two artifacts):
//   - no __stcs: default store policy preserves L2 write absorption
//   - no within-CTA path mixing: a CTA is either a TMA CTA or an STG CTA
// CTAs [0, 9216):   one 16 KB tile each, single cp.async.bulk (exact R2 path)
// CTAs [9216,11008): 1792 pure-STG CTAs, grid-stride float4 stores over the
//                    remaining 7168 tiles (7,340,032 float4; 16 per thread)

__device__ __forceinline__ uint32_t smem_u32(const void* p) {
    uint32_t a;
    asm("{ .reg .u64 t; cvta.to.shared.u64 t, %1; cvt.u32.u64 %0, t; }"
        : "=r"(a) : "l"(p));
    return a;
}

static constexpr uint32_t NTILES    = 16384;            // 4096 floats each
static constexpr uint32_t TMA_TILES = 9216;             // CTAs [0, TMA_TILES)
static constexpr uint32_t STG_CTAS  = 1792;
static constexpr uint32_t TOTAL_F4  = NTILES * 1024u;   // 16,777,216
static constexpr uint32_t STG_BASE  = TMA_TILES * 1024u;// 9,437,184

__global__ __launch_bounds__(256)
void expander_hybrid2_kernel(const float* __restrict__ A, float* __restrict__ out)
{
    __shared__ __align__(128) float4 buf[1024];   // 16 KB (TMA CTAs only)

    const uint32_t cta = blockIdx.x;
    const uint32_t t   = threadIdx.x;

    if (cta < TMA_TILES) {
        // ---------------- TMA CTA: exact R2 path ----------------
        const uint32_t c = cta;
        // Thread t fills float4 slots 4t..4t+3; slot f -> A col (f&127)>>1.
        const float2 av = *reinterpret_cast<const float2*>(
            A + (c << 6) + ((2u * t) & 63u));

        const float4 v0 = make_float4(av.x, av.x, av.x, av.x);
        const float4 v1 = make_float4(av.y, av.y, av.y, av.y);
        buf[4u * t + 0] = v0;
        buf[4u * t + 1] = v0;
        buf[4u * t + 2] = v1;
        buf[4u * t + 3] = v1;

        __syncthreads();

        if (t == 0) {
            asm volatile("fence.proxy.async.shared::cta;" ::: "memory");
            const uint32_t s = smem_u32(buf);
            const float* dst = out + ((size_t)c << 12);
            asm volatile(
                "cp.async.bulk.global.shared::cta.bulk_group [%0], [%1], %2;"
                :: "l"(dst), "r"(s), "n"(16384) : "memory");
            asm volatile("cp.async.bulk.commit_group;" ::: "memory");
            asm volatile("cp.async.bulk.wait_group 0;" ::: "memory");
        }
    } else {
        // ---------------- STG CTA: default-policy coalesced stores ----------------
        float4* out4 = reinterpret_cast<float4*>(out);
        const uint32_t tid    = ((cta - TMA_TILES) << 8) + t;  // [0, 458752)
        const uint32_t stride = STG_CTAS << 8;                 // 458,752

        #pragma unroll 4
        for (uint32_t i = STG_BASE + tid; i < TOTAL_F4; i += stride) {
            const uint32_t c4  = i & 127u;          // float4 col in row
            const uint32_t row = (i >> 7) & 511u;   // output row
            const uint32_t bc  = i >> 16;           // fused (b,c)
            const float v = __ldg(A + ((bc << 12) | ((row >> 3) << 6) | (c4 >> 1)));
            out4[i] = make_float4(v, v, v, v);
        }
    }
}

extern "C" void kernel_launch(void* const* d_in, const int* in_sizes, int n_in,
                              void* d_out, int out_size)
{
    const float* A = (const float*)d_in[0];   // (16,16,64,64) fp32
    float* out = (float*)d_out;               // (16,16,512,512) fp32

    expander_hybrid2_kernel<<<TMA_TILES + STG_CTAS, 256>>>(A, out);
}